// round 1
// baseline (speedup 1.0000x reference)
#include <cuda_runtime.h>
#include <cstddef>

#define NN 50000
#define NE 600000
#define D  128

// Scratch (module-load static allocation: allowed)
__device__ float g_msum[(size_t)NN * D];
__device__ float g_h[(size_t)NN * D];
__device__ float g_deg[NN];   // holds degree, then 1/max(deg,1)

// ---------------------------------------------------------------------------
// zero kernels (dedicated so we don't need symbol addresses for these)
// ---------------------------------------------------------------------------
__global__ void k_zero_msum() {
    int i = blockIdx.x * blockDim.x + threadIdx.x;
    int stride = gridDim.x * blockDim.x;
    float4 z = make_float4(0.f, 0.f, 0.f, 0.f);
    const int n4 = (NN * D) / 4;
    for (int idx = i; idx < n4; idx += stride)
        reinterpret_cast<float4*>(g_msum)[idx] = z;
}

__global__ void k_zero_deg() {
    int i = blockIdx.x * blockDim.x + threadIdx.x;
    if (i < NN) g_deg[i] = 0.f;
}

// ---------------------------------------------------------------------------
// degree count + invert
// ---------------------------------------------------------------------------
__global__ void k_count(const int* __restrict__ dst) {
    int e = blockIdx.x * blockDim.x + threadIdx.x;
    if (e < NE) atomicAdd(&g_deg[dst[e]], 1.0f);
}

__global__ void k_inv() {
    int i = blockIdx.x * blockDim.x + threadIdx.x;
    if (i < NN) {
        float d = g_deg[i];
        g_deg[i] = 1.0f / fmaxf(d, 1.0f);
    }
}

// ---------------------------------------------------------------------------
// scatter: one warp per edge. Gather h[src] (float4/lane), atomicAdd into
// g_msum[dst]. h table (25.6MB) is L2-resident.
// ---------------------------------------------------------------------------
__global__ void k_scatter(const float* __restrict__ h,
                          const int* __restrict__ src,
                          const int* __restrict__ dst) {
    int warp = (blockIdx.x * blockDim.x + threadIdx.x) >> 5;
    int lane = threadIdx.x & 31;
    if (warp >= NE) return;
    int s = __ldg(&src[warp]);
    int d = __ldg(&dst[warp]);
    float4 v = reinterpret_cast<const float4*>(h + (size_t)s * D)[lane];
    float* mp = g_msum + (size_t)d * D + lane * 4;
    atomicAdd(mp + 0, v.x);
    atomicAdd(mp + 1, v.y);
    atomicAdd(mp + 2, v.z);
    atomicAdd(mp + 3, v.w);
}

// ---------------------------------------------------------------------------
// fused layer: out[n] = h[n] @ Ws + (msum[n]*deg_inv[n]) @ Wn + b  (+ReLU)
// Both 128x128 fp32 weights live in dynamic SMEM (128KB) + per-warp row
// staging (64KB). 512 threads = 16 warps/block; each warp handles 4 nodes
// per iteration; each lane owns output columns [4*lane .. 4*lane+3].
// ---------------------------------------------------------------------------
#define WPB 16  // warps per block

template <bool RELU>
__global__ void __launch_bounds__(512, 1)
k_layer(const float* __restrict__ h,
        const float* __restrict__ Ws,
        const float* __restrict__ Wn,
        const float* __restrict__ bias,
        float* __restrict__ out) {
    extern __shared__ float smem[];
    float* sWs = smem;                // 16384 floats
    float* sWn = smem + 16384;        // 16384 floats
    float* stg = smem + 32768;        // WPB*4*256 = 16384 floats

    // stage weights
    for (int i = threadIdx.x; i < 16384 / 4; i += blockDim.x) {
        reinterpret_cast<float4*>(sWs)[i] = reinterpret_cast<const float4*>(Ws)[i];
        reinterpret_cast<float4*>(sWn)[i] = reinterpret_cast<const float4*>(Wn)[i];
    }
    __syncthreads();

    const int wid = threadIdx.x >> 5;
    const int lane = threadIdx.x & 31;
    const int gwarp = blockIdx.x * WPB + wid;
    const int nwarps = gridDim.x * WPB;
    float* myStg = stg + wid * 4 * 256;  // per warp: 4 nodes x (128 h + 128 m)

    const float4 bv = reinterpret_cast<const float4*>(bias)[lane];

    for (int n0 = gwarp * 4; n0 < NN; n0 += nwarps * 4) {
        __syncwarp();
        // stage 4 node rows (h and scaled msum) into smem
#pragma unroll
        for (int i = 0; i < 4; i++) {
            int n = n0 + i;
            if (n < NN) {
                float dinv = g_deg[n];
                float4 hv = reinterpret_cast<const float4*>(h + (size_t)n * D)[lane];
                float4 mv = reinterpret_cast<const float4*>(g_msum + (size_t)n * D)[lane];
                reinterpret_cast<float4*>(myStg + i * 256)[lane] = hv;
                float4 mm = make_float4(mv.x * dinv, mv.y * dinv, mv.z * dinv, mv.w * dinv);
                reinterpret_cast<float4*>(myStg + i * 256 + 128)[lane] = mm;
            }
        }
        __syncwarp();

        float4 a0 = bv, a1 = bv, a2 = bv, a3 = bv;
#pragma unroll 4
        for (int k = 0; k < D; k++) {
            float4 ws = reinterpret_cast<float4*>(sWs)[k * 32 + lane];
            float4 wn = reinterpret_cast<float4*>(sWn)[k * 32 + lane];
            float h0 = myStg[0 * 256 + k], m0 = myStg[0 * 256 + 128 + k];
            float h1 = myStg[1 * 256 + k], m1 = myStg[1 * 256 + 128 + k];
            float h2 = myStg[2 * 256 + k], m2 = myStg[2 * 256 + 128 + k];
            float h3 = myStg[3 * 256 + k], m3 = myStg[3 * 256 + 128 + k];

            a0.x = fmaf(h0, ws.x, fmaf(m0, wn.x, a0.x));
            a0.y = fmaf(h0, ws.y, fmaf(m0, wn.y, a0.y));
            a0.z = fmaf(h0, ws.z, fmaf(m0, wn.z, a0.z));
            a0.w = fmaf(h0, ws.w, fmaf(m0, wn.w, a0.w));

            a1.x = fmaf(h1, ws.x, fmaf(m1, wn.x, a1.x));
            a1.y = fmaf(h1, ws.y, fmaf(m1, wn.y, a1.y));
            a1.z = fmaf(h1, ws.z, fmaf(m1, wn.z, a1.z));
            a1.w = fmaf(h1, ws.w, fmaf(m1, wn.w, a1.w));

            a2.x = fmaf(h2, ws.x, fmaf(m2, wn.x, a2.x));
            a2.y = fmaf(h2, ws.y, fmaf(m2, wn.y, a2.y));
            a2.z = fmaf(h2, ws.z, fmaf(m2, wn.z, a2.z));
            a2.w = fmaf(h2, ws.w, fmaf(m2, wn.w, a2.w));

            a3.x = fmaf(h3, ws.x, fmaf(m3, wn.x, a3.x));
            a3.y = fmaf(h3, ws.y, fmaf(m3, wn.y, a3.y));
            a3.z = fmaf(h3, ws.z, fmaf(m3, wn.z, a3.z));
            a3.w = fmaf(h3, ws.w, fmaf(m3, wn.w, a3.w));
        }

#pragma unroll
        for (int i = 0; i < 4; i++) {
            int n = n0 + i;
            if (n >= NN) continue;
            float4 a = (i == 0) ? a0 : (i == 1) ? a1 : (i == 2) ? a2 : a3;
            if (RELU) {
                a.x = fmaxf(a.x, 0.f);
                a.y = fmaxf(a.y, 0.f);
                a.z = fmaxf(a.z, 0.f);
                a.w = fmaxf(a.w, 0.f);
            }
            reinterpret_cast<float4*>(out + (size_t)n * D)[lane] = a;
        }
    }
}

// ---------------------------------------------------------------------------
// launch
// ---------------------------------------------------------------------------
extern "C" void kernel_launch(void* const* d_in, const int* in_sizes, int n_in,
                              void* d_out, int out_size) {
    const float* feat = (const float*)d_in[0];
    const int* src = (const int*)d_in[1];
    const int* dst = (const int*)d_in[2];
    const float* Ws1 = (const float*)d_in[3];
    const float* Wn1 = (const float*)d_in[4];
    const float* b1  = (const float*)d_in[5];
    const float* Ws2 = (const float*)d_in[6];
    const float* Wn2 = (const float*)d_in[7];
    const float* b2  = (const float*)d_in[8];
    const float* Ws3 = (const float*)d_in[9];
    const float* Wn3 = (const float*)d_in[10];
    const float* b3  = (const float*)d_in[11];
    float* out = (float*)d_out;

    float* h_dev = nullptr;
    cudaGetSymbolAddress((void**)&h_dev, g_h);

    const size_t SMEM = (16384 + 16384 + WPB * 4 * 256) * sizeof(float); // 192KB
    cudaFuncSetAttribute(k_layer<true>,  cudaFuncAttributeMaxDynamicSharedMemorySize, (int)SMEM);
    cudaFuncSetAttribute(k_layer<false>, cudaFuncAttributeMaxDynamicSharedMemorySize, (int)SMEM);

    // degree
    k_zero_deg<<<(NN + 255) / 256, 256>>>();
    k_count<<<(NE + 255) / 256, 256>>>(dst);
    k_inv<<<(NN + 255) / 256, 256>>>();

    const int scatterBlocks = (NE + 7) / 8;  // 8 warps/block, warp per edge

    // layer 1: feat -> g_h (ReLU)
    k_zero_msum<<<1024, 256>>>();
    k_scatter<<<scatterBlocks, 256>>>(feat, src, dst);
    k_layer<true><<<148, 512, SMEM>>>(feat, Ws1, Wn1, b1, h_dev);

    // layer 2: g_h -> g_h (ReLU)
    k_zero_msum<<<1024, 256>>>();
    k_scatter<<<scatterBlocks, 256>>>(h_dev, src, dst);
    k_layer<true><<<148, 512, SMEM>>>(h_dev, Ws2, Wn2, b2, h_dev);

    // layer 3: g_h -> out (no ReLU)
    k_zero_msum<<<1024, 256>>>();
    k_scatter<<<scatterBlocks, 256>>>(h_dev, src, dst);
    k_layer<false><<<148, 512, SMEM>>>(h_dev, Ws3, Wn3, b3, out);
}

// round 2
// speedup vs baseline: 1.8823x; 1.8823x over previous
#include <cuda_runtime.h>
#include <cstddef>

#define NN 50000
#define NE 600000
#define D  128
#define WPB 16     // warps per block in layer kernel
#define NODES 5    // nodes per warp per iteration

// static device scratch (allowed; no runtime allocation)
__device__ float g_h1[(size_t)NN * D];
__device__ float g_h2[(size_t)NN * D];
__device__ int   g_degi[NN];
__device__ float g_dinv[NN];
__device__ int   g_rowptr[NN + 1];
__device__ int   g_cursor[NN];
__device__ int   g_csrc[NE];

// ---------------------------------------------------------------------------
__global__ void k_zero_degi() {
    int i = blockIdx.x * blockDim.x + threadIdx.x;
    if (i < NN) g_degi[i] = 0;
}

__global__ void k_count(const int* __restrict__ dst) {
    int e = blockIdx.x * blockDim.x + threadIdx.x;
    if (e < NE) atomicAdd(&g_degi[dst[e]], 1);
}

// single-block exclusive scan of degrees -> rowptr/cursor, plus deg_inv
__global__ void __launch_bounds__(1024, 1) k_scan() {
    __shared__ int wsum[32];
    __shared__ int carry_s;
    const int tid = threadIdx.x, lane = tid & 31, wid = tid >> 5;
    if (tid == 0) carry_s = 0;
    __syncthreads();
    for (int base = 0; base < NN; base += 1024) {
        int i = base + tid;
        int v = (i < NN) ? g_degi[i] : 0;
        int x = v;
#pragma unroll
        for (int o = 1; o < 32; o <<= 1) {
            int y = __shfl_up_sync(0xffffffffu, x, o);
            if (lane >= o) x += y;
        }
        if (lane == 31) wsum[wid] = x;
        __syncthreads();
        if (wid == 0) {
            int w = wsum[lane];
#pragma unroll
            for (int o = 1; o < 32; o <<= 1) {
                int y = __shfl_up_sync(0xffffffffu, w, o);
                if (lane >= o) w += y;
            }
            wsum[lane] = w;
        }
        __syncthreads();
        int off = (wid > 0) ? wsum[wid - 1] : 0;
        int incl = x + off;
        int carry = carry_s;
        if (i < NN) {
            int ex = carry + incl - v;
            g_rowptr[i] = ex;
            g_cursor[i] = ex;
            g_dinv[i] = 1.0f / fmaxf((float)v, 1.0f);
        }
        __syncthreads();
        if (tid == 1023) carry_s = carry + incl;
        __syncthreads();
    }
    if (threadIdx.x == 0) g_rowptr[NN] = carry_s;
}

__global__ void k_fill(const int* __restrict__ src, const int* __restrict__ dst) {
    int e = blockIdx.x * blockDim.x + threadIdx.x;
    if (e < NE) {
        int d = dst[e];
        int pos = atomicAdd(&g_cursor[d], 1);
        g_csrc[pos] = src[e];
    }
}

// ---------------------------------------------------------------------------
// fused layer: gather-aggregate (CSR) + dual GEMM + bias (+ReLU)
// out[n] = h[n] @ Ws + (mean_{e:dst=n} h[src_e]) @ Wn + b
// ---------------------------------------------------------------------------
template <bool RELU>
__global__ void __launch_bounds__(512, 1)
k_layer(const float* __restrict__ h,
        const float* __restrict__ Ws,
        const float* __restrict__ Wn,
        const float* __restrict__ bias,
        float* __restrict__ out) {
    extern __shared__ float smem[];
    float* sWs = smem;                 // 16384 floats
    float* sWn = smem + 16384;         // 16384 floats
    float* stg = smem + 32768;         // WPB*NODES*256 floats

    for (int i = threadIdx.x; i < 16384 / 4; i += blockDim.x) {
        reinterpret_cast<float4*>(sWs)[i] = reinterpret_cast<const float4*>(Ws)[i];
        reinterpret_cast<float4*>(sWn)[i] = reinterpret_cast<const float4*>(Wn)[i];
    }
    __syncthreads();

    const int wid = threadIdx.x >> 5;
    const int lane = threadIdx.x & 31;
    const int gwarp = blockIdx.x * WPB + wid;
    const int nwarps = gridDim.x * WPB;
    float* myStg = stg + wid * NODES * 256;

    const float4 bv = reinterpret_cast<const float4*>(bias)[lane];

    for (int n0 = gwarp * NODES; n0 < NN; n0 += nwarps * NODES) {
        __syncwarp();
        // stage NODES rows: h row + gathered mean-neighbor row
#pragma unroll
        for (int i = 0; i < NODES; i++) {
            int n = n0 + i;
            float4 hv = make_float4(0.f, 0.f, 0.f, 0.f);
            float4 mv = make_float4(0.f, 0.f, 0.f, 0.f);
            if (n < NN) {
                hv = reinterpret_cast<const float4*>(h + (size_t)n * D)[lane];
                int e = g_rowptr[n];
                const int s1 = g_rowptr[n + 1];
                for (; e + 2 <= s1; e += 2) {
                    int sa = g_csrc[e];
                    int sb = g_csrc[e + 1];
                    float4 va = reinterpret_cast<const float4*>(h + (size_t)sa * D)[lane];
                    float4 vb = reinterpret_cast<const float4*>(h + (size_t)sb * D)[lane];
                    mv.x += va.x; mv.y += va.y; mv.z += va.z; mv.w += va.w;
                    mv.x += vb.x; mv.y += vb.y; mv.z += vb.z; mv.w += vb.w;
                }
                if (e < s1) {
                    int sa = g_csrc[e];
                    float4 va = reinterpret_cast<const float4*>(h + (size_t)sa * D)[lane];
                    mv.x += va.x; mv.y += va.y; mv.z += va.z; mv.w += va.w;
                }
                float dinv = g_dinv[n];
                mv.x *= dinv; mv.y *= dinv; mv.z *= dinv; mv.w *= dinv;
            }
            reinterpret_cast<float4*>(myStg + i * 256)[lane] = hv;
            reinterpret_cast<float4*>(myStg + i * 256 + 128)[lane] = mv;
        }
        __syncwarp();

        float4 acc[NODES];
#pragma unroll
        for (int i = 0; i < NODES; i++) acc[i] = bv;

#pragma unroll 4
        for (int k = 0; k < D; k++) {
            float4 ws = reinterpret_cast<float4*>(sWs)[k * 32 + lane];
            float4 wn = reinterpret_cast<float4*>(sWn)[k * 32 + lane];
#pragma unroll
            for (int i = 0; i < NODES; i++) {
                float hk = myStg[i * 256 + k];
                float mk = myStg[i * 256 + 128 + k];
                acc[i].x = fmaf(hk, ws.x, fmaf(mk, wn.x, acc[i].x));
                acc[i].y = fmaf(hk, ws.y, fmaf(mk, wn.y, acc[i].y));
                acc[i].z = fmaf(hk, ws.z, fmaf(mk, wn.z, acc[i].z));
                acc[i].w = fmaf(hk, ws.w, fmaf(mk, wn.w, acc[i].w));
            }
        }

#pragma unroll
        for (int i = 0; i < NODES; i++) {
            int n = n0 + i;
            if (n >= NN) continue;
            float4 a = acc[i];
            if (RELU) {
                a.x = fmaxf(a.x, 0.f);
                a.y = fmaxf(a.y, 0.f);
                a.z = fmaxf(a.z, 0.f);
                a.w = fmaxf(a.w, 0.f);
            }
            reinterpret_cast<float4*>(out + (size_t)n * D)[lane] = a;
        }
    }
}

// ---------------------------------------------------------------------------
extern "C" void kernel_launch(void* const* d_in, const int* in_sizes, int n_in,
                              void* d_out, int out_size) {
    const float* feat = (const float*)d_in[0];
    const int* src = (const int*)d_in[1];
    const int* dst = (const int*)d_in[2];
    const float* Ws1 = (const float*)d_in[3];
    const float* Wn1 = (const float*)d_in[4];
    const float* b1  = (const float*)d_in[5];
    const float* Ws2 = (const float*)d_in[6];
    const float* Wn2 = (const float*)d_in[7];
    const float* b2  = (const float*)d_in[8];
    const float* Ws3 = (const float*)d_in[9];
    const float* Wn3 = (const float*)d_in[10];
    const float* b3  = (const float*)d_in[11];
    float* out = (float*)d_out;

    float *h1 = nullptr, *h2 = nullptr;
    cudaGetSymbolAddress((void**)&h1, g_h1);
    cudaGetSymbolAddress((void**)&h2, g_h2);

    const size_t SMEM = (16384 + 16384 + (size_t)WPB * NODES * 256) * sizeof(float); // 208KB
    cudaFuncSetAttribute(k_layer<true>,  cudaFuncAttributeMaxDynamicSharedMemorySize, (int)SMEM);
    cudaFuncSetAttribute(k_layer<false>, cudaFuncAttributeMaxDynamicSharedMemorySize, (int)SMEM);

    // CSR build
    k_zero_degi<<<(NN + 255) / 256, 256>>>();
    k_count<<<(NE + 255) / 256, 256>>>(dst);
    k_scan<<<1, 1024>>>();
    k_fill<<<(NE + 255) / 256, 256>>>(src, dst);

    // layers (fused aggregate + GEMM)
    k_layer<true><<<148, 512, SMEM>>>(feat, Ws1, Wn1, b1, h1);
    k_layer<true><<<148, 512, SMEM>>>(h1,   Ws2, Wn2, b2, h2);
    k_layer<false><<<148, 512, SMEM>>>(h2,  Ws3, Wn3, b3, out);
}

// round 4
// speedup vs baseline: 2.7243x; 1.4473x over previous
#include <cuda_runtime.h>
#include <cuda_bf16.h>
#include <cstdint>
#include <cstddef>

#define NN 50000
#define NE 600000
#define D  128
#define NTILES ((NN + 127) / 128)   // 391
#define THREADS 512

// SMEM layout (bytes): 6 buffers of 128 rows x 272B pitch (128 bf16 + 8 pad)
#define PB 272
#define XH_OFF 0
#define XL_OFF 34816
#define WSH_OFF 69632
#define WSL_OFF 104448
#define WNH_OFF 139264
#define WNL_OFF 174080
#define SMEM_BYTES 208896

// ---------------------------------------------------------------------------
// static device scratch
// ---------------------------------------------------------------------------
__device__ float g_h1[(size_t)NN * D];
__device__ float g_h2[(size_t)NN * D];
__device__ int   g_degi[NN];
__device__ float g_dinv[NN];
__device__ int   g_rowptr[NN + 1];
__device__ int   g_cursor[NN];
__device__ int   g_csrc[NE];
__device__ __nv_bfloat16 g_Wth[6 * D * D];  // transposed [n][k], hi part
__device__ __nv_bfloat16 g_Wtl[6 * D * D];  // residual lo part

// ---------------------------------------------------------------------------
// warp-mma helpers (plain sm_80+ ISA — no arch-'a' features)
// ---------------------------------------------------------------------------
__device__ __forceinline__ void ldsm4(uint32_t* r, uint32_t addr) {
    asm volatile("ldmatrix.sync.aligned.m8n8.x4.shared.b16 {%0,%1,%2,%3}, [%4];"
                 : "=r"(r[0]), "=r"(r[1]), "=r"(r[2]), "=r"(r[3]) : "r"(addr));
}

__device__ __forceinline__ void mma16816(float* c, const uint32_t* a, const uint32_t* b) {
    asm volatile(
        "mma.sync.aligned.m16n8k16.row.col.f32.bf16.bf16.f32 "
        "{%0,%1,%2,%3}, {%4,%5,%6,%7}, {%8,%9}, {%0,%1,%2,%3};"
        : "+f"(c[0]), "+f"(c[1]), "+f"(c[2]), "+f"(c[3])
        : "r"(a[0]), "r"(a[1]), "r"(a[2]), "r"(a[3]), "r"(b[0]), "r"(b[1]));
}

__device__ __forceinline__ uint32_t smem_u32(const void* p) {
    return (uint32_t)__cvta_generic_to_shared(p);
}

// split (x,y) fp32 pair -> packed bf16x2 hi + bf16x2 lo residual
__device__ __forceinline__ uint32_t split2(float x, float y, uint32_t& lo) {
    __nv_bfloat162 h = __float22bfloat162_rn(make_float2(x, y));
    float2 hf = __bfloat1622float2(h);
    __nv_bfloat162 l = __float22bfloat162_rn(make_float2(x - hf.x, y - hf.y));
    lo = reinterpret_cast<uint32_t&>(l);
    return reinterpret_cast<uint32_t&>(h);
}

// ---------------------------------------------------------------------------
// CSR build
// ---------------------------------------------------------------------------
__global__ void k_zero_degi() {
    int i = blockIdx.x * blockDim.x + threadIdx.x;
    if (i < NN) g_degi[i] = 0;
}

__global__ void k_count(const int* __restrict__ dst) {
    int e = blockIdx.x * blockDim.x + threadIdx.x;
    if (e < NE) atomicAdd(&g_degi[dst[e]], 1);
}

__global__ void __launch_bounds__(1024, 1) k_scan() {
    __shared__ int wsum[32];
    __shared__ int carry_s;
    const int tid = threadIdx.x, lane = tid & 31, wid = tid >> 5;
    if (tid == 0) carry_s = 0;
    __syncthreads();
    for (int base = 0; base < NN; base += 1024) {
        int i = base + tid;
        int v = (i < NN) ? g_degi[i] : 0;
        int x = v;
#pragma unroll
        for (int o = 1; o < 32; o <<= 1) {
            int y = __shfl_up_sync(0xffffffffu, x, o);
            if (lane >= o) x += y;
        }
        if (lane == 31) wsum[wid] = x;
        __syncthreads();
        if (wid == 0) {
            int w = wsum[lane];
#pragma unroll
            for (int o = 1; o < 32; o <<= 1) {
                int y = __shfl_up_sync(0xffffffffu, w, o);
                if (lane >= o) w += y;
            }
            wsum[lane] = w;
        }
        __syncthreads();
        int off = (wid > 0) ? wsum[wid - 1] : 0;
        int incl = x + off;
        int carry = carry_s;
        if (i < NN) {
            int ex = carry + incl - v;
            g_rowptr[i] = ex;
            g_cursor[i] = ex;
            g_dinv[i] = 1.0f / fmaxf((float)v, 1.0f);
        }
        __syncthreads();
        if (tid == 1023) carry_s = carry + incl;
        __syncthreads();
    }
    if (threadIdx.x == 0) g_rowptr[NN] = carry_s;
}

__global__ void k_fill(const int* __restrict__ src, const int* __restrict__ dst) {
    int e = blockIdx.x * blockDim.x + threadIdx.x;
    if (e < NE) {
        int d = dst[e];
        int pos = atomicAdd(&g_cursor[d], 1);
        g_csrc[pos] = src[e];
    }
}

// ---------------------------------------------------------------------------
// weight prep: transpose [k][n] -> [n][k], bf16 hi/lo split; one block/weight
// ---------------------------------------------------------------------------
__global__ void k_wprep(const float* W0, const float* W1, const float* W2,
                        const float* W3, const float* W4, const float* W5) {
    __shared__ float ts[D * 129];
    const float* W;
    switch (blockIdx.x) {
        case 0: W = W0; break; case 1: W = W1; break; case 2: W = W2; break;
        case 3: W = W3; break; case 4: W = W4; break; default: W = W5; break;
    }
    for (int idx = threadIdx.x; idx < D * D; idx += blockDim.x) {
        int k = idx >> 7, n = idx & 127;
        ts[n * 129 + k] = W[idx];
    }
    __syncthreads();
    __nv_bfloat16* oh = g_Wth + (size_t)blockIdx.x * D * D;
    __nv_bfloat16* ol = g_Wtl + (size_t)blockIdx.x * D * D;
    for (int idx = threadIdx.x; idx < D * D; idx += blockDim.x) {
        int n = idx >> 7, k = idx & 127;
        float v = ts[n * 129 + k];
        __nv_bfloat16 h = __float2bfloat16_rn(v);
        float r = v - __bfloat162float(h);
        oh[idx] = h;
        ol[idx] = __float2bfloat16_rn(r);
    }
}

// ---------------------------------------------------------------------------
// 3-pass bf16 split GEMM accumulation over one 128-k A buffer pair vs W pair
// ---------------------------------------------------------------------------
__device__ __forceinline__ void gemm3(float acc[2][4][4],
                                      uint32_t aXH, uint32_t aXL,
                                      uint32_t aWH, uint32_t aWL,
                                      uint32_t aoff0, uint32_t aoff1,
                                      uint32_t boff0, uint32_t boff1) {
#pragma unroll
    for (int ks = 0; ks < 8; ks++) {
        const uint32_t kb = ks * 32;   // 16 k-cols * 2 bytes
        uint32_t ah[8], al[8], bh[8], bl[8];
        ldsm4(ah + 0, aXH + aoff0 + kb);
        ldsm4(ah + 4, aXH + aoff1 + kb);
        ldsm4(al + 0, aXL + aoff0 + kb);
        ldsm4(al + 4, aXL + aoff1 + kb);
        ldsm4(bh + 0, aWH + boff0 + kb);
        ldsm4(bh + 4, aWH + boff1 + kb);
        ldsm4(bl + 0, aWL + boff0 + kb);
        ldsm4(bl + 4, aWL + boff1 + kb);
#pragma unroll
        for (int i = 0; i < 2; i++) {
#pragma unroll
            for (int j = 0; j < 4; j++) {
                const uint32_t* Bh = bh + (j >> 1) * 4 + (j & 1) * 2;
                const uint32_t* Bl = bl + (j >> 1) * 4 + (j & 1) * 2;
                mma16816(acc[i][j], ah + i * 4, Bh);   // hi*hi
                mma16816(acc[i][j], ah + i * 4, Bl);   // hi*lo
                mma16816(acc[i][j], al + i * 4, Bh);   // lo*hi
            }
        }
    }
}

// ---------------------------------------------------------------------------
// fused SAGE layer: out = relu?( X @ Ws + mean_neigh(X) @ Wn + b )
// ---------------------------------------------------------------------------
template <bool RELU>
__global__ void __launch_bounds__(THREADS, 1)
k_layer(const float* __restrict__ hin,
        const __nv_bfloat16* __restrict__ Wh,   // [2][128][128] (n,k) hi
        const __nv_bfloat16* __restrict__ Wl,   // lo
        const float* __restrict__ bias,
        float* __restrict__ out) {
    extern __shared__ __align__(16) char smem[];
    const int tid  = threadIdx.x;
    const int wid  = tid >> 5;
    const int lane = tid & 31;
    const int mw = wid >> 2;   // 0..3 (m warp)
    const int nw = wid & 3;    // 0..3 (n warp)
    const uint32_t sb = smem_u32(smem);

    // stage 4 weight buffers
    for (int c = tid; c < 2048; c += THREADS) {
        int row = c >> 4, k8 = (c & 15) << 3;
        uint32_t doff = row * PB + k8 * 2;
        *(uint4*)(smem + WSH_OFF + doff) = *(const uint4*)(Wh + row * D + k8);
        *(uint4*)(smem + WSL_OFF + doff) = *(const uint4*)(Wl + row * D + k8);
        *(uint4*)(smem + WNH_OFF + doff) = *(const uint4*)(Wh + 16384 + row * D + k8);
        *(uint4*)(smem + WNL_OFF + doff) = *(const uint4*)(Wl + 16384 + row * D + k8);
    }

    // per-thread bias pairs
    float2 bj[4];
#pragma unroll
    for (int j = 0; j < 4; j++)
        bj[j] = *(const float2*)(bias + nw * 32 + j * 8 + 2 * (lane & 3));

    // ldmatrix per-thread offsets
    const int quad = lane >> 3, rin = lane & 7;
    const uint32_t aoff0 = (uint32_t)((mw * 32 + (quad & 1) * 8 + rin) * PB + (quad >> 1) * 16);
    const uint32_t aoff1 = aoff0 + 16 * PB;
    const uint32_t boff0 = (uint32_t)((nw * 32 + (quad >> 1) * 8 + rin) * PB + (quad & 1) * 16);
    const uint32_t boff1 = boff0 + 16 * PB;
    __syncthreads();

    for (int tile = blockIdx.x; tile < NTILES; tile += gridDim.x) {
        const int nbase = tile * 128;

        // ---- stage X tile (hi/lo split) ----
        for (int c = tid; c < 4096; c += THREADS) {
            int row = c >> 5, kc = (c & 31) << 2;
            int n = nbase + row;
            float4 v = make_float4(0.f, 0.f, 0.f, 0.f);
            if (n < NN) v = *(const float4*)(hin + (size_t)n * D + kc);
            uint2 hi, lo;
            hi.x = split2(v.x, v.y, lo.x);
            hi.y = split2(v.z, v.w, lo.y);
            uint32_t doff = row * PB + kc * 2;
            *(uint2*)(smem + XH_OFF + doff) = hi;
            *(uint2*)(smem + XL_OFF + doff) = lo;
        }
        __syncthreads();

        float acc[2][4][4];
#pragma unroll
        for (int i = 0; i < 2; i++)
#pragma unroll
            for (int j = 0; j < 4; j++)
#pragma unroll
                for (int r = 0; r < 4; r++) acc[i][j][r] = 0.f;

        // ---- GEMM1: X @ Ws ----
        gemm3(acc, sb + XH_OFF, sb + XL_OFF, sb + WSH_OFF, sb + WSL_OFF,
              aoff0, aoff1, boff0, boff1);
        __syncthreads();

        // ---- gather mean-neighbor rows, overwrite X buffers ----
        {
            const int koff = lane << 2;
#pragma unroll 1
            for (int i = 0; i < 8; i++) {
                int rloc = wid * 8 + i;
                int n = nbase + rloc;
                float4 a = make_float4(0.f, 0.f, 0.f, 0.f);
                float4 b = make_float4(0.f, 0.f, 0.f, 0.f);
                if (n < NN) {
                    int e = g_rowptr[n];
                    const int e1 = g_rowptr[n + 1];
                    for (; e + 2 <= e1; e += 2) {
                        int s0 = g_csrc[e], s1 = g_csrc[e + 1];
                        float4 v0 = *(const float4*)(hin + (size_t)s0 * D + koff);
                        float4 v1 = *(const float4*)(hin + (size_t)s1 * D + koff);
                        a.x += v0.x; a.y += v0.y; a.z += v0.z; a.w += v0.w;
                        b.x += v1.x; b.y += v1.y; b.z += v1.z; b.w += v1.w;
                    }
                    if (e < e1) {
                        int s0 = g_csrc[e];
                        float4 v0 = *(const float4*)(hin + (size_t)s0 * D + koff);
                        a.x += v0.x; a.y += v0.y; a.z += v0.z; a.w += v0.w;
                    }
                    float di = g_dinv[n];
                    a.x = (a.x + b.x) * di; a.y = (a.y + b.y) * di;
                    a.z = (a.z + b.z) * di; a.w = (a.w + b.w) * di;
                } else {
                    a = make_float4(0.f, 0.f, 0.f, 0.f);
                }
                uint2 hi, lo;
                hi.x = split2(a.x, a.y, lo.x);
                hi.y = split2(a.z, a.w, lo.y);
                uint32_t doff = rloc * PB + lane * 8;
                *(uint2*)(smem + XH_OFF + doff) = hi;
                *(uint2*)(smem + XL_OFF + doff) = lo;
            }
        }
        __syncthreads();

        // ---- GEMM2: M @ Wn (accumulate) ----
        gemm3(acc, sb + XH_OFF, sb + XL_OFF, sb + WNH_OFF, sb + WNL_OFF,
              aoff0, aoff1, boff0, boff1);

        // ---- epilogue: bias (+relu), direct STG ----
#pragma unroll
        for (int i = 0; i < 2; i++) {
            int row0 = nbase + mw * 32 + i * 16 + (lane >> 2);
#pragma unroll
            for (int j = 0; j < 4; j++) {
                int col = nw * 32 + j * 8 + 2 * (lane & 3);
                float2 v0, v1;
                v0.x = acc[i][j][0] + bj[j].x;
                v0.y = acc[i][j][1] + bj[j].y;
                v1.x = acc[i][j][2] + bj[j].x;
                v1.y = acc[i][j][3] + bj[j].y;
                if (RELU) {
                    v0.x = fmaxf(v0.x, 0.f); v0.y = fmaxf(v0.y, 0.f);
                    v1.x = fmaxf(v1.x, 0.f); v1.y = fmaxf(v1.y, 0.f);
                }
                if (row0 < NN)
                    *(float2*)(out + (size_t)row0 * D + col) = v0;
                if (row0 + 8 < NN)
                    *(float2*)(out + (size_t)(row0 + 8) * D + col) = v1;
            }
        }
        __syncthreads();
    }
}

// ---------------------------------------------------------------------------
extern "C" void kernel_launch(void* const* d_in, const int* in_sizes, int n_in,
                              void* d_out, int out_size) {
    const float* feat = (const float*)d_in[0];
    const int* src = (const int*)d_in[1];
    const int* dst = (const int*)d_in[2];
    const float* Ws1 = (const float*)d_in[3];
    const float* Wn1 = (const float*)d_in[4];
    const float* b1  = (const float*)d_in[5];
    const float* Ws2 = (const float*)d_in[6];
    const float* Wn2 = (const float*)d_in[7];
    const float* b2  = (const float*)d_in[8];
    const float* Ws3 = (const float*)d_in[9];
    const float* Wn3 = (const float*)d_in[10];
    const float* b3  = (const float*)d_in[11];
    float* out = (float*)d_out;

    float *h1 = nullptr, *h2 = nullptr;
    __nv_bfloat16 *wh = nullptr, *wl = nullptr;
    cudaGetSymbolAddress((void**)&h1, g_h1);
    cudaGetSymbolAddress((void**)&h2, g_h2);
    cudaGetSymbolAddress((void**)&wh, g_Wth);
    cudaGetSymbolAddress((void**)&wl, g_Wtl);

    cudaFuncSetAttribute(k_layer<true>,  cudaFuncAttributeMaxDynamicSharedMemorySize, SMEM_BYTES);
    cudaFuncSetAttribute(k_layer<false>, cudaFuncAttributeMaxDynamicSharedMemorySize, SMEM_BYTES);

    // CSR build
    k_zero_degi<<<(NN + 255) / 256, 256>>>();
    k_count<<<(NE + 255) / 256, 256>>>(dst);
    k_scan<<<1, 1024>>>();
    k_fill<<<(NE + 255) / 256, 256>>>(src, dst);

    // weight transpose + bf16 hi/lo split
    k_wprep<<<6, 512>>>(Ws1, Wn1, Ws2, Wn2, Ws3, Wn3);

    // layers
    k_layer<true><<<148, THREADS, SMEM_BYTES>>>(feat, wh + 0 * 32768, wl + 0 * 32768, b1, h1);
    k_layer<true><<<148, THREADS, SMEM_BYTES>>>(h1,   wh + 1 * 32768, wl + 1 * 32768, b2, h2);
    k_layer<false><<<148, THREADS, SMEM_BYTES>>>(h2,  wh + 2 * 32768, wl + 2 * 32768, b3, out);
}

// round 5
// speedup vs baseline: 3.3000x; 1.2113x over previous
#include <cuda_runtime.h>
#include <cuda_bf16.h>
#include <cstdint>
#include <cstddef>

#define NN 50000
#define NE 600000
#define D  128
#define NTILES ((NN + 127) / 128)   // 391
#define THREADS 512
#define SCANB ((NN + 255) / 256)    // 196

// SMEM layout (bytes): 6 buffers of 128 rows x 272B pitch (128 bf16 + 8 pad)
#define PB 272
#define XH_OFF 0
#define XL_OFF 34816
#define WSH_OFF 69632
#define WSL_OFF 104448
#define WNH_OFF 139264
#define WNL_OFF 174080
#define SMEM_BYTES 208896
// epilogue fp32 staging overlays XH+XL: 128 rows x 136 floats = 69632 B
#define EPI_PITCH 136

// ---------------------------------------------------------------------------
// static device scratch
// ---------------------------------------------------------------------------
__device__ float g_h1[(size_t)NN * D];
__device__ float g_h2[(size_t)NN * D];
__device__ int   g_degi[NN];
__device__ float g_dinv[NN];
__device__ int   g_rowptr[NN + 1];
__device__ int   g_cursor[NN];
__device__ int   g_csrc[NE];
__device__ int   g_part[SCANB];
__device__ __nv_bfloat16 g_Wth[6 * D * D];  // transposed [n][k], hi part
__device__ __nv_bfloat16 g_Wtl[6 * D * D];  // residual lo part

// ---------------------------------------------------------------------------
// warp-mma helpers (plain sm_80+ ISA — no arch-'a' features)
// ---------------------------------------------------------------------------
__device__ __forceinline__ void ldsm4(uint32_t* r, uint32_t addr) {
    asm volatile("ldmatrix.sync.aligned.m8n8.x4.shared.b16 {%0,%1,%2,%3}, [%4];"
                 : "=r"(r[0]), "=r"(r[1]), "=r"(r[2]), "=r"(r[3]) : "r"(addr));
}

__device__ __forceinline__ void mma16816(float* c, const uint32_t* a, const uint32_t* b) {
    asm volatile(
        "mma.sync.aligned.m16n8k16.row.col.f32.bf16.bf16.f32 "
        "{%0,%1,%2,%3}, {%4,%5,%6,%7}, {%8,%9}, {%0,%1,%2,%3};"
        : "+f"(c[0]), "+f"(c[1]), "+f"(c[2]), "+f"(c[3])
        : "r"(a[0]), "r"(a[1]), "r"(a[2]), "r"(a[3]), "r"(b[0]), "r"(b[1]));
}

__device__ __forceinline__ uint32_t smem_u32(const void* p) {
    return (uint32_t)__cvta_generic_to_shared(p);
}

// split (x,y) fp32 pair -> packed bf16x2 hi + bf16x2 lo residual
__device__ __forceinline__ uint32_t split2(float x, float y, uint32_t& lo) {
    __nv_bfloat162 h = __float22bfloat162_rn(make_float2(x, y));
    float2 hf = __bfloat1622float2(h);
    __nv_bfloat162 l = __float22bfloat162_rn(make_float2(x - hf.x, y - hf.y));
    lo = reinterpret_cast<uint32_t&>(l);
    return reinterpret_cast<uint32_t&>(h);
}

// ---------------------------------------------------------------------------
// CSR build
// ---------------------------------------------------------------------------
__global__ void k_zero_degi() {
    int i = blockIdx.x * blockDim.x + threadIdx.x;
    if (i < NN) g_degi[i] = 0;
}

__global__ void k_count(const int* __restrict__ dst) {
    int e = blockIdx.x * blockDim.x + threadIdx.x;
    if (e < NE) atomicAdd(&g_degi[dst[e]], 1);
}

// block partial sums of degi
__global__ void k_part() {
    __shared__ int ws[8];
    int i = blockIdx.x * 256 + threadIdx.x;
    int lane = threadIdx.x & 31, wid = threadIdx.x >> 5;
    int v = (i < NN) ? g_degi[i] : 0;
#pragma unroll
    for (int o = 16; o > 0; o >>= 1) v += __shfl_down_sync(0xffffffffu, v, o);
    if (lane == 0) ws[wid] = v;
    __syncthreads();
    if (threadIdx.x < 8) {
        int s = ws[threadIdx.x];
#pragma unroll
        for (int o = 4; o > 0; o >>= 1) s += __shfl_down_sync(0xffu, s, o);
        if (threadIdx.x == 0) g_part[blockIdx.x] = s;
    }
}

// single small block: exclusive scan of SCANB partials
__global__ void k_scanp() {
    __shared__ int ws[8];
    int t = threadIdx.x, lane = t & 31, wid = t >> 5;
    int v = (t < SCANB) ? g_part[t] : 0;
    int x = v;
#pragma unroll
    for (int o = 1; o < 32; o <<= 1) {
        int y = __shfl_up_sync(0xffffffffu, x, o);
        if (lane >= o) x += y;
    }
    if (lane == 31) ws[wid] = x;
    __syncthreads();
    if (wid == 0 && lane < 8) {
        int w = ws[lane];
#pragma unroll
        for (int o = 1; o < 8; o <<= 1) {
            int y = __shfl_up_sync(0xffu, w, o);
            if (lane >= o) w += y;
        }
        ws[lane] = w;
    }
    __syncthreads();
    int off = (wid > 0) ? ws[wid - 1] : 0;
    if (t < SCANB) g_part[t] = off + x - v;   // exclusive
}

// block-level exclusive scan + global offset -> rowptr/cursor/dinv
__global__ void k_apply() {
    __shared__ int ws[8];
    int i = blockIdx.x * 256 + threadIdx.x;
    int lane = threadIdx.x & 31, wid = threadIdx.x >> 5;
    int v = (i < NN) ? g_degi[i] : 0;
    int x = v;
#pragma unroll
    for (int o = 1; o < 32; o <<= 1) {
        int y = __shfl_up_sync(0xffffffffu, x, o);
        if (lane >= o) x += y;
    }
    if (lane == 31) ws[wid] = x;
    __syncthreads();
    if (wid == 0 && lane < 8) {
        int w = ws[lane];
#pragma unroll
        for (int o = 1; o < 8; o <<= 1) {
            int y = __shfl_up_sync(0xffu, w, o);
            if (lane >= o) w += y;
        }
        ws[lane] = w;
    }
    __syncthreads();
    int off = (wid > 0) ? ws[wid - 1] : 0;
    if (i < NN) {
        int ex = g_part[blockIdx.x] + off + x - v;
        g_rowptr[i] = ex;
        g_cursor[i] = ex;
        g_dinv[i] = 1.0f / fmaxf((float)v, 1.0f);
    }
    if (blockIdx.x == 0 && threadIdx.x == 0) g_rowptr[NN] = NE;
}

__global__ void k_fill(const int* __restrict__ src, const int* __restrict__ dst) {
    int e = blockIdx.x * blockDim.x + threadIdx.x;
    if (e < NE) {
        int d = dst[e];
        int pos = atomicAdd(&g_cursor[d], 1);
        g_csrc[pos] = src[e];
    }
}

// ---------------------------------------------------------------------------
// weight prep: transpose [k][n] -> [n][k], bf16 hi/lo split; one block/weight
// ---------------------------------------------------------------------------
__global__ void k_wprep(const float* W0, const float* W1, const float* W2,
                        const float* W3, const float* W4, const float* W5) {
    __shared__ float ts[D * 129];
    const float* W;
    switch (blockIdx.x) {
        case 0: W = W0; break; case 1: W = W1; break; case 2: W = W2; break;
        case 3: W = W3; break; case 4: W = W4; break; default: W = W5; break;
    }
    for (int idx = threadIdx.x; idx < D * D; idx += blockDim.x) {
        int k = idx >> 7, n = idx & 127;
        ts[n * 129 + k] = W[idx];
    }
    __syncthreads();
    __nv_bfloat16* oh = g_Wth + (size_t)blockIdx.x * D * D;
    __nv_bfloat16* ol = g_Wtl + (size_t)blockIdx.x * D * D;
    for (int idx = threadIdx.x; idx < D * D; idx += blockDim.x) {
        int n = idx >> 7, k = idx & 127;
        float v = ts[n * 129 + k];
        __nv_bfloat16 h = __float2bfloat16_rn(v);
        float r = v - __bfloat162float(h);
        oh[idx] = h;
        ol[idx] = __float2bfloat16_rn(r);
    }
}

// ---------------------------------------------------------------------------
// one ks-step of the 3-pass split GEMM (hi*hi + hi*lo + lo*hi)
// ---------------------------------------------------------------------------
__device__ __forceinline__ void gemm3_step(float acc[2][4][4],
                                           uint32_t aXH, uint32_t aXL,
                                           uint32_t aWH, uint32_t aWL,
                                           uint32_t aoff0, uint32_t aoff1,
                                           uint32_t boff0, uint32_t boff1,
                                           uint32_t kb) {
    uint32_t ah[8], al[8], bh[8], bl[8];
    ldsm4(ah + 0, aXH + aoff0 + kb);
    ldsm4(ah + 4, aXH + aoff1 + kb);
    ldsm4(al + 0, aXL + aoff0 + kb);
    ldsm4(al + 4, aXL + aoff1 + kb);
    ldsm4(bh + 0, aWH + boff0 + kb);
    ldsm4(bh + 4, aWH + boff1 + kb);
    ldsm4(bl + 0, aWL + boff0 + kb);
    ldsm4(bl + 4, aWL + boff1 + kb);
#pragma unroll
    for (int i = 0; i < 2; i++) {
#pragma unroll
        for (int j = 0; j < 4; j++) {
            const uint32_t* Bh = bh + (j >> 1) * 4 + (j & 1) * 2;
            const uint32_t* Bl = bl + (j >> 1) * 4 + (j & 1) * 2;
            mma16816(acc[i][j], ah + i * 4, Bh);   // hi*hi
            mma16816(acc[i][j], ah + i * 4, Bl);   // hi*lo
            mma16816(acc[i][j], al + i * 4, Bh);   // lo*hi
        }
    }
}

// ---------------------------------------------------------------------------
// fused SAGE layer: out = relu?( X @ Ws + mean_neigh(X) @ Wn + b )
// gather interleaved with GEMM1 (one node per ks-step) for pipe overlap
// ---------------------------------------------------------------------------
template <bool RELU>
__global__ void __launch_bounds__(THREADS)
k_layer(const float* __restrict__ hin,
        const __nv_bfloat16* __restrict__ Wh,   // [2][128][128] (n,k) hi
        const __nv_bfloat16* __restrict__ Wl,   // lo
        const float* __restrict__ bias,
        float* __restrict__ out) {
    extern __shared__ __align__(16) char smem[];
    const int tid  = threadIdx.x;
    const int wid  = tid >> 5;
    const int lane = tid & 31;
    const int mw = wid >> 2;   // 0..3 (m warp)
    const int nw = wid & 3;    // 0..3 (n warp)
    const uint32_t sb = smem_u32(smem);

    // stage 4 weight buffers
    for (int c = tid; c < 2048; c += THREADS) {
        int row = c >> 4, k8 = (c & 15) << 3;
        uint32_t doff = row * PB + k8 * 2;
        *(uint4*)(smem + WSH_OFF + doff) = *(const uint4*)(Wh + row * D + k8);
        *(uint4*)(smem + WSL_OFF + doff) = *(const uint4*)(Wl + row * D + k8);
        *(uint4*)(smem + WNH_OFF + doff) = *(const uint4*)(Wh + 16384 + row * D + k8);
        *(uint4*)(smem + WNL_OFF + doff) = *(const uint4*)(Wl + 16384 + row * D + k8);
    }

    // per-thread bias pairs
    float2 bj[4];
#pragma unroll
    for (int j = 0; j < 4; j++)
        bj[j] = *(const float2*)(bias + nw * 32 + j * 8 + 2 * (lane & 3));

    // ldmatrix per-thread offsets
    const int quad = lane >> 3, rin = lane & 7;
    const uint32_t aoff0 = (uint32_t)((mw * 32 + (quad & 1) * 8 + rin) * PB + (quad >> 1) * 16);
    const uint32_t aoff1 = aoff0 + 16 * PB;
    const uint32_t boff0 = (uint32_t)((nw * 32 + (quad >> 1) * 8 + rin) * PB + (quad & 1) * 16);
    const uint32_t boff1 = boff0 + 16 * PB;
    const int koff = lane << 2;
    __syncthreads();

    for (int tile = blockIdx.x; tile < NTILES; tile += gridDim.x) {
        const int nbase = tile * 128;

        // ---- stage X tile (hi/lo split) ----
        for (int c = tid; c < 4096; c += THREADS) {
            int row = c >> 5, kc = (c & 31) << 2;
            int n = nbase + row;
            float4 v = make_float4(0.f, 0.f, 0.f, 0.f);
            if (n < NN) v = *(const float4*)(hin + (size_t)n * D + kc);
            uint2 hi, lo;
            hi.x = split2(v.x, v.y, lo.x);
            hi.y = split2(v.z, v.w, lo.y);
            uint32_t doff = row * PB + kc * 2;
            *(uint2*)(smem + XH_OFF + doff) = hi;
            *(uint2*)(smem + XL_OFF + doff) = lo;
        }
        __syncthreads();

        float acc[2][4][4];
#pragma unroll
        for (int i = 0; i < 2; i++)
#pragma unroll
            for (int j = 0; j < 4; j++)
#pragma unroll
                for (int r = 0; r < 4; r++) acc[i][j][r] = 0.f;

        // ---- GEMM1 interleaved with gather (one node per ks-step) ----
        uint2 mh[8], ml[8];
#pragma unroll
        for (int ks = 0; ks < 8; ks++) {
            // gather node wid*8 + ks into regs (memory pipe)
            {
                int n = nbase + (wid << 3) + ks;
                float4 a = make_float4(0.f, 0.f, 0.f, 0.f);
                if (n < NN) {
                    float4 b = make_float4(0.f, 0.f, 0.f, 0.f);
                    float4 c2 = make_float4(0.f, 0.f, 0.f, 0.f);
                    float4 d2 = make_float4(0.f, 0.f, 0.f, 0.f);
                    int e = g_rowptr[n];
                    const int e1 = g_rowptr[n + 1];
                    for (; e + 4 <= e1; e += 4) {
                        int s0 = g_csrc[e], s1 = g_csrc[e + 1];
                        int s2 = g_csrc[e + 2], s3 = g_csrc[e + 3];
                        float4 v0 = *(const float4*)(hin + (size_t)s0 * D + koff);
                        float4 v1 = *(const float4*)(hin + (size_t)s1 * D + koff);
                        float4 v2 = *(const float4*)(hin + (size_t)s2 * D + koff);
                        float4 v3 = *(const float4*)(hin + (size_t)s3 * D + koff);
                        a.x += v0.x; a.y += v0.y; a.z += v0.z; a.w += v0.w;
                        b.x += v1.x; b.y += v1.y; b.z += v1.z; b.w += v1.w;
                        c2.x += v2.x; c2.y += v2.y; c2.z += v2.z; c2.w += v2.w;
                        d2.x += v3.x; d2.y += v3.y; d2.z += v3.z; d2.w += v3.w;
                    }
                    if (e + 2 <= e1) {
                        int s0 = g_csrc[e], s1 = g_csrc[e + 1];
                        float4 v0 = *(const float4*)(hin + (size_t)s0 * D + koff);
                        float4 v1 = *(const float4*)(hin + (size_t)s1 * D + koff);
                        a.x += v0.x; a.y += v0.y; a.z += v0.z; a.w += v0.w;
                        b.x += v1.x; b.y += v1.y; b.z += v1.z; b.w += v1.w;
                        e += 2;
                    }
                    if (e < e1) {
                        int s0 = g_csrc[e];
                        float4 v0 = *(const float4*)(hin + (size_t)s0 * D + koff);
                        a.x += v0.x; a.y += v0.y; a.z += v0.z; a.w += v0.w;
                    }
                    float di = g_dinv[n];
                    a.x = (a.x + b.x + c2.x + d2.x) * di;
                    a.y = (a.y + b.y + c2.y + d2.y) * di;
                    a.z = (a.z + b.z + c2.z + d2.z) * di;
                    a.w = (a.w + b.w + c2.w + d2.w) * di;
                }
                mh[ks].x = split2(a.x, a.y, ml[ks].x);
                mh[ks].y = split2(a.z, a.w, ml[ks].y);
            }
            // one ks-step of GEMM1 (tensor pipe)
            gemm3_step(acc, sb + XH_OFF, sb + XL_OFF, sb + WSH_OFF, sb + WSL_OFF,
                       aoff0, aoff1, boff0, boff1, ks * 32);
        }
        __syncthreads();   // all GEMM1 X-reads done

        // ---- dump M rows into X buffers ----
#pragma unroll
        for (int i = 0; i < 8; i++) {
            uint32_t doff = ((wid << 3) + i) * PB + lane * 8;
            *(uint2*)(smem + XH_OFF + doff) = mh[i];
            *(uint2*)(smem + XL_OFF + doff) = ml[i];
        }
        __syncthreads();

        // ---- GEMM2: M @ Wn (accumulate) ----
#pragma unroll
        for (int ks = 0; ks < 8; ks++)
            gemm3_step(acc, sb + XH_OFF, sb + XL_OFF, sb + WNH_OFF, sb + WNL_OFF,
                       aoff0, aoff1, boff0, boff1, ks * 32);
        __syncthreads();   // all GEMM2 reads done before epilogue overwrite

        // ---- epilogue: bias (+relu) -> fp32 SMEM staging -> coalesced STG ----
        float* sepi = (float*)(smem + XH_OFF);   // [128][EPI_PITCH]
#pragma unroll
        for (int i = 0; i < 2; i++) {
            int r0 = mw * 32 + i * 16 + (lane >> 2);
#pragma unroll
            for (int j = 0; j < 4; j++) {
                int col = nw * 32 + j * 8 + 2 * (lane & 3);
                float2 v0, v1;
                v0.x = acc[i][j][0] + bj[j].x;
                v0.y = acc[i][j][1] + bj[j].y;
                v1.x = acc[i][j][2] + bj[j].x;
                v1.y = acc[i][j][3] + bj[j].y;
                if (RELU) {
                    v0.x = fmaxf(v0.x, 0.f); v0.y = fmaxf(v0.y, 0.f);
                    v1.x = fmaxf(v1.x, 0.f); v1.y = fmaxf(v1.y, 0.f);
                }
                *(float2*)(sepi + r0 * EPI_PITCH + col) = v0;
                *(float2*)(sepi + (r0 + 8) * EPI_PITCH + col) = v1;
            }
        }
        __syncthreads();
        for (int c = tid; c < 4096; c += THREADS) {
            int row = c >> 5, k0 = (c & 31) << 2;
            int n = nbase + row;
            if (n < NN) {
                float4 v = *(const float4*)(sepi + row * EPI_PITCH + k0);
                *(float4*)(out + (size_t)n * D + k0) = v;
            }
        }
        __syncthreads();
    }
}

// ---------------------------------------------------------------------------
extern "C" void kernel_launch(void* const* d_in, const int* in_sizes, int n_in,
                              void* d_out, int out_size) {
    const float* feat = (const float*)d_in[0];
    const int* src = (const int*)d_in[1];
    const int* dst = (const int*)d_in[2];
    const float* Ws1 = (const float*)d_in[3];
    const float* Wn1 = (const float*)d_in[4];
    const float* b1  = (const float*)d_in[5];
    const float* Ws2 = (const float*)d_in[6];
    const float* Wn2 = (const float*)d_in[7];
    const float* b2  = (const float*)d_in[8];
    const float* Ws3 = (const float*)d_in[9];
    const float* Wn3 = (const float*)d_in[10];
    const float* b3  = (const float*)d_in[11];
    float* out = (float*)d_out;

    float *h1 = nullptr, *h2 = nullptr;
    __nv_bfloat16 *wh = nullptr, *wl = nullptr;
    cudaGetSymbolAddress((void**)&h1, g_h1);
    cudaGetSymbolAddress((void**)&h2, g_h2);
    cudaGetSymbolAddress((void**)&wh, g_Wth);
    cudaGetSymbolAddress((void**)&wl, g_Wtl);

    cudaFuncSetAttribute(k_layer<true>,  cudaFuncAttributeMaxDynamicSharedMemorySize, SMEM_BYTES);
    cudaFuncSetAttribute(k_layer<false>, cudaFuncAttributeMaxDynamicSharedMemorySize, SMEM_BYTES);

    // CSR build (multi-block scan)
    k_zero_degi<<<(NN + 255) / 256, 256>>>();
    k_count<<<(NE + 255) / 256, 256>>>(dst);
    k_part<<<SCANB, 256>>>();
    k_scanp<<<1, 256>>>();
    k_apply<<<SCANB, 256>>>();
    k_fill<<<(NE + 255) / 256, 256>>>(src, dst);

    // weight transpose + bf16 hi/lo split
    k_wprep<<<6, 512>>>(Ws1, Wn1, Ws2, Wn2, Ws3, Wn3);

    // layers
    k_layer<true><<<148, THREADS, SMEM_BYTES>>>(feat, wh + 0 * 32768, wl + 0 * 32768, b1, h1);
    k_layer<true><<<148, THREADS, SMEM_BYTES>>>(h1,   wh + 1 * 32768, wl + 1 * 32768, b2, h2);
    k_layer<false><<<148, THREADS, SMEM_BYTES>>>(h2,  wh + 2 * 32768, wl + 2 * 32768, b3, out);
}

// round 6
// speedup vs baseline: 3.3041x; 1.0012x over previous
#include <cuda_runtime.h>
#include <cuda_bf16.h>
#include <cstdint>
#include <cstddef>

#define NN 50000
#define NE 600000
#define D  128
#define NTILES ((NN + 127) / 128)   // 391
#define THREADS 512
#define SCANB ((NN + 255) / 256)    // 196
#define NCTAS 148

// SMEM layout (bytes): 6 buffers of 128 rows x 272B pitch (128 bf16 + 8 pad)
#define PB 272
#define XH_OFF 0
#define XL_OFF 34816
#define WSH_OFF 69632
#define WSL_OFF 104448
#define WNH_OFF 139264
#define WNL_OFF 174080
#define SMEM_BYTES 208896
// epilogue fp32 staging overlays XH+XL: 128 rows x 136 floats
#define EPI_PITCH 136

// ---------------------------------------------------------------------------
// static device scratch
// ---------------------------------------------------------------------------
__device__ float g_h1[(size_t)NN * D];
__device__ float g_h2[(size_t)NN * D];
__device__ int   g_degi[NN];
__device__ float g_dinv[NN];
__device__ int   g_rowptr[NN + 1];
__device__ int   g_cursor[NN];
__device__ int   g_csrc[NE];
__device__ unsigned long long g_desc[SCANB];   // lookback: flag<<32 | value
__device__ unsigned g_barcnt;
__device__ unsigned g_barphase;
__device__ __nv_bfloat16 g_Wth[6 * D * D];  // transposed [n][k], hi part
__device__ __nv_bfloat16 g_Wtl[6 * D * D];  // residual lo part

// ---------------------------------------------------------------------------
// helpers
// ---------------------------------------------------------------------------
__device__ __forceinline__ void ldsm4(uint32_t* r, uint32_t addr) {
    asm volatile("ldmatrix.sync.aligned.m8n8.x4.shared.b16 {%0,%1,%2,%3}, [%4];"
                 : "=r"(r[0]), "=r"(r[1]), "=r"(r[2]), "=r"(r[3]) : "r"(addr));
}

__device__ __forceinline__ void mma16816(float* c, const uint32_t* a, const uint32_t* b) {
    asm volatile(
        "mma.sync.aligned.m16n8k16.row.col.f32.bf16.bf16.f32 "
        "{%0,%1,%2,%3}, {%4,%5,%6,%7}, {%8,%9}, {%0,%1,%2,%3};"
        : "+f"(c[0]), "+f"(c[1]), "+f"(c[2]), "+f"(c[3])
        : "r"(a[0]), "r"(a[1]), "r"(a[2]), "r"(a[3]), "r"(b[0]), "r"(b[1]));
}

__device__ __forceinline__ uint32_t smem_u32(const void* p) {
    return (uint32_t)__cvta_generic_to_shared(p);
}

__device__ __forceinline__ uint32_t split2(float x, float y, uint32_t& lo) {
    __nv_bfloat162 h = __float22bfloat162_rn(make_float2(x, y));
    float2 hf = __bfloat1622float2(h);
    __nv_bfloat162 l = __float22bfloat162_rn(make_float2(x - hf.x, y - hf.y));
    lo = reinterpret_cast<uint32_t&>(l);
    return reinterpret_cast<uint32_t&>(h);
}

// device-wide barrier for persistent kernel (cumulative count, no reset)
__device__ __forceinline__ void grid_barrier(unsigned gen) {
    __syncthreads();
    if (threadIdx.x == 0) {
        __threadfence();
        unsigned old = atomicAdd(&g_barcnt, 1u);
        if (old == gen * NCTAS - 1u) {
            atomicExch(&g_barphase, gen);
        } else {
            while (atomicAdd(&g_barphase, 0u) < gen) {}
        }
        __threadfence();
    }
    __syncthreads();
}

// ---------------------------------------------------------------------------
// kernel 1: degree count (2 edges/thread) + weight transpose/split (fused)
// ---------------------------------------------------------------------------
__global__ void k_count_wprep(const int* __restrict__ dst,
                              const float* W0, const float* W1, const float* W2,
                              const float* W3, const float* W4, const float* W5) {
    int i = blockIdx.x * blockDim.x + threadIdx.x;
    if (i < NE / 2) {
        int2 d = ((const int2*)dst)[i];
        atomicAdd(&g_degi[d.x], 1);
        atomicAdd(&g_degi[d.y], 1);
    }
    // weight prep: 6 * 16384 = 98304 elems, idx = w*16384 + n*128 + k
    if (i < 6 * D * D) {
        int w = i >> 14;
        int r = i & 16383;
        int n = r >> 7, k = r & 127;
        const float* W;
        switch (w) {
            case 0: W = W0; break; case 1: W = W1; break; case 2: W = W2; break;
            case 3: W = W3; break; case 4: W = W4; break; default: W = W5; break;
        }
        float v = W[k * D + n];
        __nv_bfloat16 h = __float2bfloat16_rn(v);
        float res = v - __bfloat162float(h);
        g_Wth[i] = h;
        g_Wtl[i] = __float2bfloat16_rn(res);
    }
}

// ---------------------------------------------------------------------------
// kernel 2: single-pass exclusive scan (decoupled lookback), 196 blocks
// ---------------------------------------------------------------------------
__global__ void __launch_bounds__(256) k_scan() {
    __shared__ int ws[8];
    __shared__ int s_boff;
    const int b = blockIdx.x;
    const int i = b * 256 + threadIdx.x;
    const int lane = threadIdx.x & 31, wid = threadIdx.x >> 5;

    int v = (i < NN) ? g_degi[i] : 0;
    int x = v;
#pragma unroll
    for (int o = 1; o < 32; o <<= 1) {
        int y = __shfl_up_sync(0xffffffffu, x, o);
        if (lane >= o) x += y;
    }
    if (lane == 31) ws[wid] = x;
    __syncthreads();
    if (wid == 0 && lane < 8) {
        int w = ws[lane];
#pragma unroll
        for (int o = 1; o < 8; o <<= 1) {
            int y = __shfl_up_sync(0xffu, w, o);
            if (lane >= o) w += y;
        }
        ws[lane] = w;
    }
    __syncthreads();
    int off = (wid > 0) ? ws[wid - 1] : 0;
    int S = ws[7];   // block total

    if (threadIdx.x == 0) {
        int boff = 0;
        if (b == 0) {
            atomicExch(&g_desc[0], (2ULL << 32) | (unsigned)S);
        } else {
            atomicExch(&g_desc[b], (1ULL << 32) | (unsigned)S);
            int j = b - 1;
            long long sum = 0;
            while (true) {
                unsigned long long d = atomicAdd(&g_desc[j], 0ULL);
                unsigned f = (unsigned)(d >> 32);
                if (f == 0) continue;
                sum += (unsigned)(d & 0xffffffffULL);
                if (f == 2) break;
                j--;
            }
            boff = (int)sum;
            atomicExch(&g_desc[b], (2ULL << 32) | (unsigned)(boff + S));
        }
        s_boff = boff;
    }
    __syncthreads();
    int boff = s_boff;
    if (i < NN) {
        int ex = boff + off + x - v;
        g_rowptr[i] = ex;
        g_cursor[i] = ex;
        g_dinv[i] = 1.0f / fmaxf((float)v, 1.0f);
    }
    if (b == 0 && threadIdx.x == 0) g_rowptr[NN] = NE;
}

// ---------------------------------------------------------------------------
// kernel 3: CSR fill (2 edges/thread) + reset scratch state for next replay
// ---------------------------------------------------------------------------
__global__ void k_fill(const int* __restrict__ src, const int* __restrict__ dst) {
    int i = blockIdx.x * blockDim.x + threadIdx.x;
    if (i < NE / 2) {
        int2 d = ((const int2*)dst)[i];
        int2 s = ((const int2*)src)[i];
        int p0 = atomicAdd(&g_cursor[d.x], 1);
        g_csrc[p0] = s.x;
        int p1 = atomicAdd(&g_cursor[d.y], 1);
        g_csrc[p1] = s.y;
    }
    // reset state consumed earlier in this replay (safe: producers/consumers
    // of these are all in kernels that precede k_fill or are bss-zero initially)
    if (i < NN) g_degi[i] = 0;
    if (i < SCANB) g_desc[i] = 0ULL;
    if (i == 0) { g_barcnt = 0u; g_barphase = 0u; }
}

// ---------------------------------------------------------------------------
// one ks-step of the 3-pass split GEMM (hi*hi + hi*lo + lo*hi)
// ---------------------------------------------------------------------------
__device__ __forceinline__ void gemm3_step(float acc[2][4][4],
                                           uint32_t aXH, uint32_t aXL,
                                           uint32_t aWH, uint32_t aWL,
                                           uint32_t aoff0, uint32_t aoff1,
                                           uint32_t boff0, uint32_t boff1,
                                           uint32_t kb) {
    uint32_t ah[8], al[8], bh[8], bl[8];
    ldsm4(ah + 0, aXH + aoff0 + kb);
    ldsm4(ah + 4, aXH + aoff1 + kb);
    ldsm4(al + 0, aXL + aoff0 + kb);
    ldsm4(al + 4, aXL + aoff1 + kb);
    ldsm4(bh + 0, aWH + boff0 + kb);
    ldsm4(bh + 4, aWH + boff1 + kb);
    ldsm4(bl + 0, aWL + boff0 + kb);
    ldsm4(bl + 4, aWL + boff1 + kb);
#pragma unroll
    for (int i = 0; i < 2; i++) {
#pragma unroll
        for (int j = 0; j < 4; j++) {
            const uint32_t* Bh = bh + (j >> 1) * 4 + (j & 1) * 2;
            const uint32_t* Bl = bl + (j >> 1) * 4 + (j & 1) * 2;
            mma16816(acc[i][j], ah + i * 4, Bh);
            mma16816(acc[i][j], ah + i * 4, Bl);
            mma16816(acc[i][j], al + i * 4, Bh);
        }
    }
}

// ---------------------------------------------------------------------------
// kernel 4 (persistent): all 3 fused SAGE layers with device barriers
// ---------------------------------------------------------------------------
__global__ void __launch_bounds__(THREADS)
k_layers(const float* __restrict__ feat,
         const float* __restrict__ b1,
         const float* __restrict__ b2,
         const float* __restrict__ b3,
         float* __restrict__ out) {
    extern __shared__ __align__(16) char smem[];
    const int tid  = threadIdx.x;
    const int wid  = tid >> 5;
    const int lane = tid & 31;
    const int mw = wid >> 2;
    const int nw = wid & 3;
    const uint32_t sb = smem_u32(smem);

    // ldmatrix per-thread offsets
    const int quad = lane >> 3, rin = lane & 7;
    const uint32_t aoff0 = (uint32_t)((mw * 32 + (quad & 1) * 8 + rin) * PB + (quad >> 1) * 16);
    const uint32_t aoff1 = aoff0 + 16 * PB;
    const uint32_t boff0 = (uint32_t)((nw * 32 + (quad >> 1) * 8 + rin) * PB + (quad & 1) * 16);
    const uint32_t boff1 = boff0 + 16 * PB;
    const int koff = lane << 2;

    for (int L = 0; L < 3; L++) {
        const float* hin  = (L == 0) ? feat : ((L == 1) ? g_h1 : g_h2);
        float* hout       = (L == 0) ? g_h1 : ((L == 1) ? g_h2 : out);
        const float* bias = (L == 0) ? b1 : ((L == 1) ? b2 : b3);
        const bool relu = (L < 2);
        const __nv_bfloat16* Wh = g_Wth + (size_t)L * 2 * D * D;
        const __nv_bfloat16* Wl = g_Wtl + (size_t)L * 2 * D * D;

        // stage this layer's 4 weight buffers
        for (int c = tid; c < 2048; c += THREADS) {
            int row = c >> 4, k8 = (c & 15) << 3;
            uint32_t doff = row * PB + k8 * 2;
            *(uint4*)(smem + WSH_OFF + doff) = *(const uint4*)(Wh + row * D + k8);
            *(uint4*)(smem + WSL_OFF + doff) = *(const uint4*)(Wl + row * D + k8);
            *(uint4*)(smem + WNH_OFF + doff) = *(const uint4*)(Wh + 16384 + row * D + k8);
            *(uint4*)(smem + WNL_OFF + doff) = *(const uint4*)(Wl + 16384 + row * D + k8);
        }
        float2 bj[4];
#pragma unroll
        for (int j = 0; j < 4; j++)
            bj[j] = *(const float2*)(bias + nw * 32 + j * 8 + 2 * (lane & 3));
        __syncthreads();

        for (int tile = blockIdx.x; tile < NTILES; tile += gridDim.x) {
            const int nbase = tile * 128;

            // ---- stage X tile (hi/lo split) ----
            for (int c = tid; c < 4096; c += THREADS) {
                int row = c >> 5, kc = (c & 31) << 2;
                int n = nbase + row;
                float4 v = make_float4(0.f, 0.f, 0.f, 0.f);
                if (n < NN) v = *(const float4*)(hin + (size_t)n * D + kc);
                uint2 hi, lo;
                hi.x = split2(v.x, v.y, lo.x);
                hi.y = split2(v.z, v.w, lo.y);
                uint32_t doff = row * PB + kc * 2;
                *(uint2*)(smem + XH_OFF + doff) = hi;
                *(uint2*)(smem + XL_OFF + doff) = lo;
            }
            __syncthreads();

            float acc[2][4][4];
#pragma unroll
            for (int i = 0; i < 2; i++)
#pragma unroll
                for (int j = 0; j < 4; j++)
#pragma unroll
                    for (int r = 0; r < 4; r++) acc[i][j][r] = 0.f;

            // ---- GEMM1 interleaved with gather (one node per ks-step) ----
            uint2 mh[8], ml[8];
#pragma unroll
            for (int ks = 0; ks < 8; ks++) {
                {
                    int n = nbase + (wid << 3) + ks;
                    float4 a = make_float4(0.f, 0.f, 0.f, 0.f);
                    if (n < NN) {
                        float4 b = make_float4(0.f, 0.f, 0.f, 0.f);
                        float4 c2 = make_float4(0.f, 0.f, 0.f, 0.f);
                        float4 d2 = make_float4(0.f, 0.f, 0.f, 0.f);
                        int e = g_rowptr[n];
                        const int e1 = g_rowptr[n + 1];
                        for (; e + 4 <= e1; e += 4) {
                            int s0 = g_csrc[e], s1 = g_csrc[e + 1];
                            int s2 = g_csrc[e + 2], s3 = g_csrc[e + 3];
                            float4 v0 = *(const float4*)(hin + (size_t)s0 * D + koff);
                            float4 v1 = *(const float4*)(hin + (size_t)s1 * D + koff);
                            float4 v2 = *(const float4*)(hin + (size_t)s2 * D + koff);
                            float4 v3 = *(const float4*)(hin + (size_t)s3 * D + koff);
                            a.x += v0.x; a.y += v0.y; a.z += v0.z; a.w += v0.w;
                            b.x += v1.x; b.y += v1.y; b.z += v1.z; b.w += v1.w;
                            c2.x += v2.x; c2.y += v2.y; c2.z += v2.z; c2.w += v2.w;
                            d2.x += v3.x; d2.y += v3.y; d2.z += v3.z; d2.w += v3.w;
                        }
                        if (e + 2 <= e1) {
                            int s0 = g_csrc[e], s1 = g_csrc[e + 1];
                            float4 v0 = *(const float4*)(hin + (size_t)s0 * D + koff);
                            float4 v1 = *(const float4*)(hin + (size_t)s1 * D + koff);
                            a.x += v0.x; a.y += v0.y; a.z += v0.z; a.w += v0.w;
                            b.x += v1.x; b.y += v1.y; b.z += v1.z; b.w += v1.w;
                            e += 2;
                        }
                        if (e < e1) {
                            int s0 = g_csrc[e];
                            float4 v0 = *(const float4*)(hin + (size_t)s0 * D + koff);
                            a.x += v0.x; a.y += v0.y; a.z += v0.z; a.w += v0.w;
                        }
                        float di = g_dinv[n];
                        a.x = (a.x + b.x + c2.x + d2.x) * di;
                        a.y = (a.y + b.y + c2.y + d2.y) * di;
                        a.z = (a.z + b.z + c2.z + d2.z) * di;
                        a.w = (a.w + b.w + c2.w + d2.w) * di;
                    }
                    mh[ks].x = split2(a.x, a.y, ml[ks].x);
                    mh[ks].y = split2(a.z, a.w, ml[ks].y);
                }
                gemm3_step(acc, sb + XH_OFF, sb + XL_OFF, sb + WSH_OFF, sb + WSL_OFF,
                           aoff0, aoff1, boff0, boff1, ks * 32);
            }
            __syncthreads();

            // ---- dump M rows into X buffers ----
#pragma unroll
            for (int i = 0; i < 8; i++) {
                uint32_t doff = ((wid << 3) + i) * PB + lane * 8;
                *(uint2*)(smem + XH_OFF + doff) = mh[i];
                *(uint2*)(smem + XL_OFF + doff) = ml[i];
            }
            __syncthreads();

            // ---- GEMM2: M @ Wn ----
#pragma unroll
            for (int ks = 0; ks < 8; ks++)
                gemm3_step(acc, sb + XH_OFF, sb + XL_OFF, sb + WNH_OFF, sb + WNL_OFF,
                           aoff0, aoff1, boff0, boff1, ks * 32);
            __syncthreads();

            // ---- epilogue: bias (+relu) -> fp32 SMEM -> coalesced STG ----
            float* sepi = (float*)(smem + XH_OFF);
#pragma unroll
            for (int i = 0; i < 2; i++) {
                int r0 = mw * 32 + i * 16 + (lane >> 2);
#pragma unroll
                for (int j = 0; j < 4; j++) {
                    int col = nw * 32 + j * 8 + 2 * (lane & 3);
                    float2 v0, v1;
                    v0.x = acc[i][j][0] + bj[j].x;
                    v0.y = acc[i][j][1] + bj[j].y;
                    v1.x = acc[i][j][2] + bj[j].x;
                    v1.y = acc[i][j][3] + bj[j].y;
                    if (relu) {
                        v0.x = fmaxf(v0.x, 0.f); v0.y = fmaxf(v0.y, 0.f);
                        v1.x = fmaxf(v1.x, 0.f); v1.y = fmaxf(v1.y, 0.f);
                    }
                    *(float2*)(sepi + r0 * EPI_PITCH + col) = v0;
                    *(float2*)(sepi + (r0 + 8) * EPI_PITCH + col) = v1;
                }
            }
            __syncthreads();
            for (int c = tid; c < 4096; c += THREADS) {
                int row = c >> 5, k0 = (c & 31) << 2;
                int n = nbase + row;
                if (n < NN) {
                    float4 v = *(const float4*)(sepi + row * EPI_PITCH + k0);
                    *(float4*)(hout + (size_t)n * D + k0) = v;
                }
            }
            __syncthreads();
        }

        if (L < 2) grid_barrier(L + 1);
    }
}

// ---------------------------------------------------------------------------
extern "C" void kernel_launch(void* const* d_in, const int* in_sizes, int n_in,
                              void* d_out, int out_size) {
    const float* feat = (const float*)d_in[0];
    const int* src = (const int*)d_in[1];
    const int* dst = (const int*)d_in[2];
    const float* Ws1 = (const float*)d_in[3];
    const float* Wn1 = (const float*)d_in[4];
    const float* b1  = (const float*)d_in[5];
    const float* Ws2 = (const float*)d_in[6];
    const float* Wn2 = (const float*)d_in[7];
    const float* b2  = (const float*)d_in[8];
    const float* Ws3 = (const float*)d_in[9];
    const float* Wn3 = (const float*)d_in[10];
    const float* b3  = (const float*)d_in[11];
    float* out = (float*)d_out;

    cudaFuncSetAttribute(k_layers, cudaFuncAttributeMaxDynamicSharedMemorySize, SMEM_BYTES);

    const int EBLK = (NE / 2 + 255) / 256;   // 1172 blocks, 2 edges/thread

    // 1: count degrees + weight prep (fused, independent work)
    k_count_wprep<<<EBLK, 256>>>(dst, Ws1, Wn1, Ws2, Wn2, Ws3, Wn3);
    // 2: single-pass decoupled-lookback scan -> rowptr/cursor/dinv
    k_scan<<<SCANB, 256>>>();
    // 3: CSR fill + reset replay state
    k_fill<<<EBLK, 256>>>(src, dst);
    // 4: persistent fused 3-layer kernel
    k_layers<<<NCTAS, THREADS, SMEM_BYTES>>>(feat, b1, b2, b3, out);
}

// round 7
// speedup vs baseline: 3.4984x; 1.0588x over previous
#include <cuda_runtime.h>
#include <cuda_bf16.h>
#include <cstdint>
#include <cstddef>

#define NN 50000
#define NE 600000
#define D  128
#define NTILES ((NN + 127) / 128)   // 391
#define THREADS 512
#define SCANB ((NN + 255) / 256)    // 196
#define NCTAS 148

// SMEM layout (bytes): 6 buffers of 128 rows x 272B pitch (128 bf16 + 8 pad)
#define PB 272
#define XH_OFF 0
#define XL_OFF 34816
#define WSH_OFF 69632
#define WSL_OFF 104448
#define WNH_OFF 139264
#define WNL_OFF 174080
#define EIDX_OFF 208896            // 4096 ints = 16KB tile edge-index cache
#define EIDX_CAP 4096
#define SMEM_BYTES (208896 + 16384)   // 225280
// epilogue fp32 staging overlays XH+XL: 128 rows x 136 floats = 69632 B
#define EPI_PITCH 136

// ---------------------------------------------------------------------------
// static device scratch
// ---------------------------------------------------------------------------
__device__ float g_h1[(size_t)NN * D];
__device__ float g_h2[(size_t)NN * D];
__device__ int   g_degi[NN];
__device__ float g_dinv[NN];
__device__ int   g_rowptr[NN + 1];
__device__ int   g_cursor[NN];
__device__ int   g_csrc[NE];
__device__ unsigned long long g_desc[SCANB];   // lookback: flag<<32 | value
__device__ unsigned g_barcnt;
__device__ unsigned g_barphase;
__device__ int g_tilectr[3];
__device__ __nv_bfloat16 g_Wth[6 * D * D];  // transposed [n][k], hi part
__device__ __nv_bfloat16 g_Wtl[6 * D * D];  // residual lo part

// ---------------------------------------------------------------------------
// helpers
// ---------------------------------------------------------------------------
__device__ __forceinline__ void ldsm4(uint32_t* r, uint32_t addr) {
    asm volatile("ldmatrix.sync.aligned.m8n8.x4.shared.b16 {%0,%1,%2,%3}, [%4];"
                 : "=r"(r[0]), "=r"(r[1]), "=r"(r[2]), "=r"(r[3]) : "r"(addr));
}

__device__ __forceinline__ void mma16816(float* c, const uint32_t* a, const uint32_t* b) {
    asm volatile(
        "mma.sync.aligned.m16n8k16.row.col.f32.bf16.bf16.f32 "
        "{%0,%1,%2,%3}, {%4,%5,%6,%7}, {%8,%9}, {%0,%1,%2,%3};"
        : "+f"(c[0]), "+f"(c[1]), "+f"(c[2]), "+f"(c[3])
        : "r"(a[0]), "r"(a[1]), "r"(a[2]), "r"(a[3]), "r"(b[0]), "r"(b[1]));
}

__device__ __forceinline__ uint32_t smem_u32(const void* p) {
    return (uint32_t)__cvta_generic_to_shared(p);
}

__device__ __forceinline__ uint32_t split2(float x, float y, uint32_t& lo) {
    __nv_bfloat162 h = __float22bfloat162_rn(make_float2(x, y));
    float2 hf = __bfloat1622float2(h);
    __nv_bfloat162 l = __float22bfloat162_rn(make_float2(x - hf.x, y - hf.y));
    lo = reinterpret_cast<uint32_t&>(l);
    return reinterpret_cast<uint32_t&>(h);
}

// device-wide barrier for persistent kernel (cumulative count, no reset)
__device__ __forceinline__ void grid_barrier(unsigned gen) {
    __syncthreads();
    if (threadIdx.x == 0) {
        __threadfence();
        unsigned old = atomicAdd(&g_barcnt, 1u);
        if (old == gen * NCTAS - 1u) {
            atomicExch(&g_barphase, gen);
        } else {
            while (atomicAdd(&g_barphase, 0u) < gen) {}
        }
        __threadfence();
    }
    __syncthreads();
}

// ---------------------------------------------------------------------------
// kernel 1: degree count (2 edges/thread) + weight transpose/split (fused)
// ---------------------------------------------------------------------------
__global__ void k_count_wprep(const int* __restrict__ dst,
                              const float* W0, const float* W1, const float* W2,
                              const float* W3, const float* W4, const float* W5) {
    int i = blockIdx.x * blockDim.x + threadIdx.x;
    if (i < NE / 2) {
        int2 d = ((const int2*)dst)[i];
        atomicAdd(&g_degi[d.x], 1);
        atomicAdd(&g_degi[d.y], 1);
    }
    if (i < 6 * D * D) {
        int w = i >> 14;
        int r = i & 16383;
        int n = r >> 7, k = r & 127;
        const float* W;
        switch (w) {
            case 0: W = W0; break; case 1: W = W1; break; case 2: W = W2; break;
            case 3: W = W3; break; case 4: W = W4; break; default: W = W5; break;
        }
        float v = W[k * D + n];
        __nv_bfloat16 h = __float2bfloat16_rn(v);
        float res = v - __bfloat162float(h);
        g_Wth[i] = h;
        g_Wtl[i] = __float2bfloat16_rn(res);
    }
}

// ---------------------------------------------------------------------------
// kernel 2: single-pass exclusive scan (decoupled lookback), 196 blocks
// ---------------------------------------------------------------------------
__global__ void __launch_bounds__(256) k_scan() {
    __shared__ int ws[8];
    __shared__ int s_boff;
    const int b = blockIdx.x;
    const int i = b * 256 + threadIdx.x;
    const int lane = threadIdx.x & 31, wid = threadIdx.x >> 5;

    int v = (i < NN) ? g_degi[i] : 0;
    int x = v;
#pragma unroll
    for (int o = 1; o < 32; o <<= 1) {
        int y = __shfl_up_sync(0xffffffffu, x, o);
        if (lane >= o) x += y;
    }
    if (lane == 31) ws[wid] = x;
    __syncthreads();
    if (wid == 0 && lane < 8) {
        int w = ws[lane];
#pragma unroll
        for (int o = 1; o < 8; o <<= 1) {
            int y = __shfl_up_sync(0xffu, w, o);
            if (lane >= o) w += y;
        }
        ws[lane] = w;
    }
    __syncthreads();
    int off = (wid > 0) ? ws[wid - 1] : 0;
    int S = ws[7];

    if (threadIdx.x == 0) {
        int boff = 0;
        if (b == 0) {
            atomicExch(&g_desc[0], (2ULL << 32) | (unsigned)S);
        } else {
            atomicExch(&g_desc[b], (1ULL << 32) | (unsigned)S);
            int j = b - 1;
            long long sum = 0;
            while (true) {
                unsigned long long d = atomicAdd(&g_desc[j], 0ULL);
                unsigned f = (unsigned)(d >> 32);
                if (f == 0) continue;
                sum += (unsigned)(d & 0xffffffffULL);
                if (f == 2) break;
                j--;
            }
            boff = (int)sum;
            atomicExch(&g_desc[b], (2ULL << 32) | (unsigned)(boff + S));
        }
        s_boff = boff;
    }
    __syncthreads();
    int boff = s_boff;
    if (i < NN) {
        int ex = boff + off + x - v;
        g_rowptr[i] = ex;
        g_cursor[i] = ex;
        g_dinv[i] = 1.0f / fmaxf((float)v, 1.0f);
    }
    if (b == 0 && threadIdx.x == 0) g_rowptr[NN] = NE;
}

// ---------------------------------------------------------------------------
// kernel 3: CSR fill (2 edges/thread) + reset scratch state for next replay
// ---------------------------------------------------------------------------
__global__ void k_fill(const int* __restrict__ src, const int* __restrict__ dst) {
    int i = blockIdx.x * blockDim.x + threadIdx.x;
    if (i < NE / 2) {
        int2 d = ((const int2*)dst)[i];
        int2 s = ((const int2*)src)[i];
        int p0 = atomicAdd(&g_cursor[d.x], 1);
        g_csrc[p0] = s.x;
        int p1 = atomicAdd(&g_cursor[d.y], 1);
        g_csrc[p1] = s.y;
    }
    if (i < NN) g_degi[i] = 0;
    if (i < SCANB) g_desc[i] = 0ULL;
    if (i < 3) g_tilectr[i] = 0;
    if (i == 3) { g_barcnt = 0u; g_barphase = 0u; }
}

// ---------------------------------------------------------------------------
// one ks-step of the 3-pass split GEMM (hi*hi + hi*lo + lo*hi)
// ---------------------------------------------------------------------------
__device__ __forceinline__ void gemm3_step(float acc[2][4][4],
                                           uint32_t aXH, uint32_t aXL,
                                           uint32_t aWH, uint32_t aWL,
                                           uint32_t aoff0, uint32_t aoff1,
                                           uint32_t boff0, uint32_t boff1,
                                           uint32_t kb) {
    uint32_t ah[8], al[8], bh[8], bl[8];
    ldsm4(ah + 0, aXH + aoff0 + kb);
    ldsm4(ah + 4, aXH + aoff1 + kb);
    ldsm4(al + 0, aXL + aoff0 + kb);
    ldsm4(al + 4, aXL + aoff1 + kb);
    ldsm4(bh + 0, aWH + boff0 + kb);
    ldsm4(bh + 4, aWH + boff1 + kb);
    ldsm4(bl + 0, aWL + boff0 + kb);
    ldsm4(bl + 4, aWL + boff1 + kb);
#pragma unroll
    for (int i = 0; i < 2; i++) {
#pragma unroll
        for (int j = 0; j < 4; j++) {
            const uint32_t* Bh = bh + (j >> 1) * 4 + (j & 1) * 2;
            const uint32_t* Bl = bl + (j >> 1) * 4 + (j & 1) * 2;
            mma16816(acc[i][j], ah + i * 4, Bh);
            mma16816(acc[i][j], ah + i * 4, Bl);
            mma16816(acc[i][j], al + i * 4, Bh);
        }
    }
}

// ---------------------------------------------------------------------------
// kernel 4 (persistent): all 3 fused SAGE layers, dynamic tiles, dev barriers
// ---------------------------------------------------------------------------
__global__ void __launch_bounds__(THREADS)
k_layers(const float* __restrict__ feat,
         const float* __restrict__ b1,
         const float* __restrict__ b2,
         const float* __restrict__ b3,
         float* __restrict__ out) {
    extern __shared__ __align__(16) char smem[];
    __shared__ int sRp[129];
    __shared__ int s_tile;
    int* sEidx = (int*)(smem + EIDX_OFF);

    const int tid  = threadIdx.x;
    const int wid  = tid >> 5;
    const int lane = tid & 31;
    const int mw = wid >> 2;
    const int nw = wid & 3;
    const uint32_t sb = smem_u32(smem);

    const int quad = lane >> 3, rin = lane & 7;
    const uint32_t aoff0 = (uint32_t)((mw * 32 + (quad & 1) * 8 + rin) * PB + (quad >> 1) * 16);
    const uint32_t aoff1 = aoff0 + 16 * PB;
    const uint32_t boff0 = (uint32_t)((nw * 32 + (quad >> 1) * 8 + rin) * PB + (quad & 1) * 16);
    const uint32_t boff1 = boff0 + 16 * PB;
    const int koff = lane << 2;

    for (int L = 0; L < 3; L++) {
        const float* hin  = (L == 0) ? feat : ((L == 1) ? g_h1 : g_h2);
        float* hout       = (L == 0) ? g_h1 : ((L == 1) ? g_h2 : out);
        const float* bias = (L == 0) ? b1 : ((L == 1) ? b2 : b3);
        const bool relu = (L < 2);
        const __nv_bfloat16* Wh = g_Wth + (size_t)L * 2 * D * D;
        const __nv_bfloat16* Wl = g_Wtl + (size_t)L * 2 * D * D;

        // stage this layer's 4 weight buffers
        for (int c = tid; c < 2048; c += THREADS) {
            int row = c >> 4, k8 = (c & 15) << 3;
            uint32_t doff = row * PB + k8 * 2;
            *(uint4*)(smem + WSH_OFF + doff) = *(const uint4*)(Wh + row * D + k8);
            *(uint4*)(smem + WSL_OFF + doff) = *(const uint4*)(Wl + row * D + k8);
            *(uint4*)(smem + WNH_OFF + doff) = *(const uint4*)(Wh + 16384 + row * D + k8);
            *(uint4*)(smem + WNL_OFF + doff) = *(const uint4*)(Wl + 16384 + row * D + k8);
        }
        float2 bj[4];
#pragma unroll
        for (int j = 0; j < 4; j++)
            bj[j] = *(const float2*)(bias + nw * 32 + j * 8 + 2 * (lane & 3));

        while (true) {
            __syncthreads();
            if (tid == 0) s_tile = atomicAdd(&g_tilectr[L], 1);
            __syncthreads();
            const int tile = s_tile;
            if (tile >= NTILES) break;
            const int nbase = tile * 128;

            // ---- stage X tile (hi/lo split) + rowptr slice + edge indices ----
            for (int c = tid; c < 4096; c += THREADS) {
                int row = c >> 5, kc = (c & 31) << 2;
                int n = nbase + row;
                float4 v = make_float4(0.f, 0.f, 0.f, 0.f);
                if (n < NN) v = *(const float4*)(hin + (size_t)n * D + kc);
                uint2 hi, lo;
                hi.x = split2(v.x, v.y, lo.x);
                hi.y = split2(v.z, v.w, lo.y);
                uint32_t doff = row * PB + kc * 2;
                *(uint2*)(smem + XH_OFF + doff) = hi;
                *(uint2*)(smem + XL_OFF + doff) = lo;
            }
            if (tid <= 128) {
                int n = nbase + tid;
                sRp[tid] = g_rowptr[(n < NN) ? n : NN];
            }
            __syncthreads();
            const int e0base = sRp[0];
            const int ecnt = sRp[128] - e0base;
            const bool inSmem = (ecnt <= EIDX_CAP);
            if (inSmem) {
                for (int e = tid; e < ecnt; e += THREADS)
                    sEidx[e] = g_csrc[e0base + e];
            }
            __syncthreads();

            float acc[2][4][4];
#pragma unroll
            for (int i = 0; i < 2; i++)
#pragma unroll
                for (int j = 0; j < 4; j++)
#pragma unroll
                    for (int r = 0; r < 4; r++) acc[i][j][r] = 0.f;

            // ---- GEMM1 interleaved with gather (one node per ks-step) ----
            uint2 mh[8], ml[8];
#pragma unroll
            for (int ks = 0; ks < 8; ks++) {
                {
                    int r = (wid << 3) + ks;
                    int n = nbase + r;
                    float4 a = make_float4(0.f, 0.f, 0.f, 0.f);
                    if (n < NN) {
                        int b0 = sRp[r];
                        const int b1e = sRp[r + 1];
                        const int* __restrict__ idxp =
                            inSmem ? (sEidx + (b0 - e0base)) : (g_csrc + b0);
                        const int cnt = b1e - b0;
                        float4 b = make_float4(0.f, 0.f, 0.f, 0.f);
                        float4 c2 = make_float4(0.f, 0.f, 0.f, 0.f);
                        float4 d2 = make_float4(0.f, 0.f, 0.f, 0.f);
                        int e = 0;
                        for (; e + 4 <= cnt; e += 4) {
                            int s0 = idxp[e], s1 = idxp[e + 1];
                            int s2 = idxp[e + 2], s3 = idxp[e + 3];
                            float4 v0 = *(const float4*)(hin + (size_t)s0 * D + koff);
                            float4 v1 = *(const float4*)(hin + (size_t)s1 * D + koff);
                            float4 v2 = *(const float4*)(hin + (size_t)s2 * D + koff);
                            float4 v3 = *(const float4*)(hin + (size_t)s3 * D + koff);
                            a.x += v0.x; a.y += v0.y; a.z += v0.z; a.w += v0.w;
                            b.x += v1.x; b.y += v1.y; b.z += v1.z; b.w += v1.w;
                            c2.x += v2.x; c2.y += v2.y; c2.z += v2.z; c2.w += v2.w;
                            d2.x += v3.x; d2.y += v3.y; d2.z += v3.z; d2.w += v3.w;
                        }
                        if (e + 2 <= cnt) {
                            int s0 = idxp[e], s1 = idxp[e + 1];
                            float4 v0 = *(const float4*)(hin + (size_t)s0 * D + koff);
                            float4 v1 = *(const float4*)(hin + (size_t)s1 * D + koff);
                            a.x += v0.x; a.y += v0.y; a.z += v0.z; a.w += v0.w;
                            b.x += v1.x; b.y += v1.y; b.z += v1.z; b.w += v1.w;
                            e += 2;
                        }
                        if (e < cnt) {
                            int s0 = idxp[e];
                            float4 v0 = *(const float4*)(hin + (size_t)s0 * D + koff);
                            a.x += v0.x; a.y += v0.y; a.z += v0.z; a.w += v0.w;
                        }
                        float di = g_dinv[n];
                        a.x = (a.x + b.x + c2.x + d2.x) * di;
                        a.y = (a.y + b.y + c2.y + d2.y) * di;
                        a.z = (a.z + b.z + c2.z + d2.z) * di;
                        a.w = (a.w + b.w + c2.w + d2.w) * di;
                    }
                    mh[ks].x = split2(a.x, a.y, ml[ks].x);
                    mh[ks].y = split2(a.z, a.w, ml[ks].y);
                }
                gemm3_step(acc, sb + XH_OFF, sb + XL_OFF, sb + WSH_OFF, sb + WSL_OFF,
                           aoff0, aoff1, boff0, boff1, ks * 32);
            }
            __syncthreads();

            // ---- dump M rows into X buffers ----
#pragma unroll
            for (int i = 0; i < 8; i++) {
                uint32_t doff = ((wid << 3) + i) * PB + lane * 8;
                *(uint2*)(smem + XH_OFF + doff) = mh[i];
                *(uint2*)(smem + XL_OFF + doff) = ml[i];
            }
            __syncthreads();

            // ---- GEMM2: M @ Wn ----
#pragma unroll
            for (int ks = 0; ks < 8; ks++)
                gemm3_step(acc, sb + XH_OFF, sb + XL_OFF, sb + WNH_OFF, sb + WNL_OFF,
                           aoff0, aoff1, boff0, boff1, ks * 32);
            __syncthreads();

            // ---- epilogue: bias (+relu) -> fp32 SMEM -> coalesced STG ----
            float* sepi = (float*)(smem + XH_OFF);
#pragma unroll
            for (int i = 0; i < 2; i++) {
                int r0 = mw * 32 + i * 16 + (lane >> 2);
#pragma unroll
                for (int j = 0; j < 4; j++) {
                    int col = nw * 32 + j * 8 + 2 * (lane & 3);
                    float2 v0, v1;
                    v0.x = acc[i][j][0] + bj[j].x;
                    v0.y = acc[i][j][1] + bj[j].y;
                    v1.x = acc[i][j][2] + bj[j].x;
                    v1.y = acc[i][j][3] + bj[j].y;
                    if (relu) {
                        v0.x = fmaxf(v0.x, 0.f); v0.y = fmaxf(v0.y, 0.f);
                        v1.x = fmaxf(v1.x, 0.f); v1.y = fmaxf(v1.y, 0.f);
                    }
                    *(float2*)(sepi + r0 * EPI_PITCH + col) = v0;
                    *(float2*)(sepi + (r0 + 8) * EPI_PITCH + col) = v1;
                }
            }
            __syncthreads();
            for (int c = tid; c < 4096; c += THREADS) {
                int row = c >> 5, k0 = (c & 31) << 2;
                int n = nbase + row;
                if (n < NN) {
                    float4 v = *(const float4*)(sepi + row * EPI_PITCH + k0);
                    *(float4*)(hout + (size_t)n * D + k0) = v;
                }
            }
        }

        if (L < 2) grid_barrier(L + 1);
    }
}

// ---------------------------------------------------------------------------
extern "C" void kernel_launch(void* const* d_in, const int* in_sizes, int n_in,
                              void* d_out, int out_size) {
    const float* feat = (const float*)d_in[0];
    const int* src = (const int*)d_in[1];
    const int* dst = (const int*)d_in[2];
    const float* Ws1 = (const float*)d_in[3];
    const float* Wn1 = (const float*)d_in[4];
    const float* b1  = (const float*)d_in[5];
    const float* Ws2 = (const float*)d_in[6];
    const float* Wn2 = (const float*)d_in[7];
    const float* b2  = (const float*)d_in[8];
    const float* Ws3 = (const float*)d_in[9];
    const float* Wn3 = (const float*)d_in[10];
    const float* b3  = (const float*)d_in[11];
    float* out = (float*)d_out;

    cudaFuncSetAttribute(k_layers, cudaFuncAttributeMaxDynamicSharedMemorySize, SMEM_BYTES);

    const int EBLK = (NE / 2 + 255) / 256;

    k_count_wprep<<<EBLK, 256>>>(dst, Ws1, Wn1, Ws2, Wn2, Ws3, Wn3);
    k_scan<<<SCANB, 256>>>();
    k_fill<<<EBLK, 256>>>(src, dst);
    k_layers<<<NCTAS, THREADS, SMEM_BYTES>>>(feat, b1, b2, b3, out);
}